// round 13
// baseline (speedup 1.0000x reference)
#include <cuda_runtime.h>
#include <cstdint>

#define Bb 32
#define Cc 32
#define Tt 2048
#define Dd 512
#define ALPHA 0.1f
#define BETA  0.9f

#define SEG   256
#define NSEG  (Tt / SEG)          // 8

// Scratch (no cudaMalloc allowed)
__device__ float g_sA[Bb*Cc*Tt];      // 0.5 * forward EWMA of diff   [b][c][t]
__device__ float g_sB[Bb*Cc*Tt];      // 0.5 * backward EWMA of diff  [b][c][t]
__device__ float g_wc[Cc*Dd];         // Wcomb c-major: g_wc[c*Dd + e]
__device__ float g_bcomb[Dd];         // W_lin @ b_ve + b_lin

#define FMA_F32X2(d, a, b, c) \
    asm("fma.rn.f32x2 %0, %1, %2, %3;" : "=l"(d) : "l"(a), "l"(b), "l"(c))

static __device__ __forceinline__ float2 unpack_f32x2(unsigned long long v) {
    float2 r;
    asm("mov.b64 {%0, %1}, %2;" : "=f"(r.x), "=f"(r.y) : "l"(v));
    return r;
}

// ---------------------------------------------------------------------------
// P: smem-tiled mini-GEMM for Wcomb = W_lin @ W_ve (c-major out) + bias.
// (measured ~4us)
// ---------------------------------------------------------------------------
#define PE 16
__global__ void __launch_bounds__(256) prep_kernel(
    const float* __restrict__ W_ve, const float* __restrict__ b_ve,
    const float* __restrict__ W_lin, const float* __restrict__ b_lin)
{
    __shared__ float wlin_sm[128 * 17];
    __shared__ float wve_sm[128 * 36];

    int tid = threadIdx.x;
    int e0 = blockIdx.x * PE;
    int tx = tid & 15;
    int ty = tid >> 4;

    float2 acc = make_float2(0.f, 0.f);

    for (int ch = 0; ch < 4; ch++) {
        int dBase = ch * 128;
        __syncthreads();

        #pragma unroll
        for (int k = 0; k < 2; k++) {
            int idx = tid + k * 256;
            int e   = idx >> 5;
            int d4  = (idx & 31) * 4;
            float4 w = *(const float4*)(W_lin + (size_t)(e0 + e) * Dd + dBase + d4);
            wlin_sm[(d4 + 0) * 17 + e] = w.x;
            wlin_sm[(d4 + 1) * 17 + e] = w.y;
            wlin_sm[(d4 + 2) * 17 + e] = w.z;
            wlin_sm[(d4 + 3) * 17 + e] = w.w;
        }
        #pragma unroll
        for (int k = 0; k < 4; k++) {
            int idx = tid + k * 256;
            int d   = idx >> 3;
            int c4  = (idx & 7) * 4;
            float4 v = *(const float4*)(W_ve + (size_t)(dBase + d) * Cc + c4);
            *(float4*)&wve_sm[d * 36 + c4] = v;
        }
        __syncthreads();

        #pragma unroll 8
        for (int dl = 0; dl < 128; dl++) {
            float  wl  = wlin_sm[dl * 17 + ty];
            float2 wv2 = *(const float2*)&wve_sm[dl * 36 + tx * 2];
            acc.x = fmaf(wl, wv2.x, acc.x);
            acc.y = fmaf(wl, wv2.y, acc.y);
        }
    }

    int e = e0 + ty;
    g_wc[(2 * tx)     * Dd + e] = acc.x;
    g_wc[(2 * tx + 1) * Dd + e] = acc.y;

    const unsigned FULL = 0xffffffffu;
    int wid  = tid >> 5;
    int lane = tid & 31;
    #pragma unroll
    for (int r = 0; r < 2; r++) {
        int eb = e0 + 2 * wid + r;
        float a = 0.f;
        #pragma unroll
        for (int i = 0; i < 16; i++) {
            int d = lane + 32 * i;
            a = fmaf(W_lin[(size_t)eb * Dd + d], b_ve[d], a);
        }
        a += __shfl_down_sync(FULL, a, 16);
        a += __shfl_down_sync(FULL, a, 8);
        a += __shfl_down_sync(FULL, a, 4);
        a += __shfl_down_sync(FULL, a, 2);
        a += __shfl_down_sync(FULL, a, 1);
        if (lane == 0) g_bcomb[eb] = a + b_lin[eb];
    }
}

// ---------------------------------------------------------------------------
// S: bidirectional EWMA of first-difference (SEG=256, E=8; measured 9.2us).
// ---------------------------------------------------------------------------
__global__ void __launch_bounds__(256) scan_kernel(const float* __restrict__ x)
{
    const unsigned FULL = 0xffffffffu;
    int g    = blockIdx.x * 8 + (threadIdx.x >> 5);
    int lane = threadIdx.x & 31;
    int bc   = g >> 4;
    int rem  = g & 15;
    int seg  = rem >> 1;
    int dir  = rem & 1;

    const float* row = x + (size_t)bc * Tt;
    int lo = seg * SEG;
    int hi = lo + SEG;

    const float q   = 0.43046721f;              // 0.9^8
    const float q2  = q * q;
    const float q4  = q2 * q2;
    const float q8  = q4 * q4;
    const float q16 = q8 * q8;
    float blE;
    {
        float p = 1.f, base = q;
        int n = lane;
        while (n) { if (n & 1) p *= base; base *= base; n >>= 1; }
        blE = p;
    }
    const float B256 = 1.9e-12f;

    if (dir == 0) {
        float* srow = g_sA + (size_t)bc * Tt;
        int t0 = (seg == 0) ? lo : (lo - SEG);
        float warpCarry = 0.f;
        for (; t0 < hi; t0 += SEG) {
            int tb = t0 + lane * 8;
            float4 a  = *(const float4*)(row + tb);
            float4 bq = *(const float4*)(row + tb + 4);
            float e[8] = {a.x, a.y, a.z, a.w, bq.x, bq.y, bq.z, bq.w};
            float prev = __shfl_up_sync(FULL, bq.w, 1);
            if (lane == 0) prev = (tb > 0) ? row[tb - 1] : 0.f;

            float L[8];
            L[0] = (tb == 0) ? 0.f : ALPHA * (e[0] - prev);
            #pragma unroll
            for (int j = 1; j < 8; j++)
                L[j] = fmaf(BETA, L[j - 1], ALPHA * (e[j] - e[j - 1]));

            float v = L[7], vo;
            vo = __shfl_up_sync(FULL, v, 1);  if (lane >= 1)  v = fmaf(q,   vo, v);
            vo = __shfl_up_sync(FULL, v, 2);  if (lane >= 2)  v = fmaf(q2,  vo, v);
            vo = __shfl_up_sync(FULL, v, 4);  if (lane >= 4)  v = fmaf(q4,  vo, v);
            vo = __shfl_up_sync(FULL, v, 8);  if (lane >= 8)  v = fmaf(q8,  vo, v);
            vo = __shfl_up_sync(FULL, v, 16); if (lane >= 16) v = fmaf(q16, vo, v);
            float vprev = __shfl_up_sync(FULL, v, 1);
            if (lane == 0) vprev = 0.f;
            float C = fmaf(blE, warpCarry, vprev);

            float F[8];
            float coef = BETA;
            #pragma unroll
            for (int j = 0; j < 8; j++) { F[j] = fmaf(coef, C, L[j]); coef *= BETA; }
            float v31 = __shfl_sync(FULL, v, 31);
            warpCarry = fmaf(B256, warpCarry, v31);

            if (t0 >= lo) {
                *(float4*)(srow + tb)     = make_float4(0.5f*F[0], 0.5f*F[1], 0.5f*F[2], 0.5f*F[3]);
                *(float4*)(srow + tb + 4) = make_float4(0.5f*F[4], 0.5f*F[5], 0.5f*F[6], 0.5f*F[7]);
            }
        }
    } else {
        float* srow = g_sB + (size_t)bc * Tt;
        bool last = (hi == Tt);
        int tt = last ? (Tt - 1) : (hi + SEG - 1);
        float warpCarry = last ? (row[Tt - 1] - row[Tt - 2]) : 0.f;
        for (; tt >= lo; tt -= SEG) {
            int tb = tt - lane * 8;
            float4 a  = *(const float4*)(row + tb - 7);
            float4 bq = *(const float4*)(row + tb - 3);
            float e[8] = {bq.w, bq.z, bq.y, bq.x, a.w, a.z, a.y, a.x};
            float prev = __shfl_down_sync(FULL, bq.w, 1);
            if (lane == 31) prev = (tb - 8 >= 0) ? row[tb - 8] : 0.f;

            float L[8];
            L[0] = ALPHA * (e[0] - e[1]);
            #pragma unroll
            for (int j = 1; j < 7; j++)
                L[j] = fmaf(BETA, L[j - 1], ALPHA * (e[j] - e[j + 1]));
            {
                float d7 = (tb - 7 == 0) ? 0.f : (e[7] - prev);
                L[7] = fmaf(BETA, L[6], ALPHA * d7);
            }

            float v = L[7], vo;
            vo = __shfl_up_sync(FULL, v, 1);  if (lane >= 1)  v = fmaf(q,   vo, v);
            vo = __shfl_up_sync(FULL, v, 2);  if (lane >= 2)  v = fmaf(q2,  vo, v);
            vo = __shfl_up_sync(FULL, v, 4);  if (lane >= 4)  v = fmaf(q4,  vo, v);
            vo = __shfl_up_sync(FULL, v, 8);  if (lane >= 8)  v = fmaf(q8,  vo, v);
            vo = __shfl_up_sync(FULL, v, 16); if (lane >= 16) v = fmaf(q16, vo, v);
            float vprev = __shfl_up_sync(FULL, v, 1);
            if (lane == 0) vprev = 0.f;
            float C = fmaf(blE, warpCarry, vprev);

            float F[8];
            float coef = BETA;
            #pragma unroll
            for (int j = 0; j < 8; j++) { F[j] = fmaf(coef, C, L[j]); coef *= BETA; }
            float v31 = __shfl_sync(FULL, v, 31);
            warpCarry = fmaf(B256, warpCarry, v31);

            if (tt < hi) {
                *(float4*)(srow + tb - 7) = make_float4(0.5f*F[7], 0.5f*F[6], 0.5f*F[5], 0.5f*F[4]);
                *(float4*)(srow + tb - 3) = make_float4(0.5f*F[3], 0.5f*F[2], 0.5f*F[1], 0.5f*F[0]);
            }
        }
    }
}

// ---------------------------------------------------------------------------
// G: FFMA2 GEMM with t-pair accumulators — NO pack stage in the mainloop.
// Block tile 128t x 128e, 256 thr, 2 CTA/SM. Thread tile 8t x 8e:
//   t = tBase + ty*8 + 2*i + h   (i=0..3 pairs, h in f32x2 lanes)
//   e = eBase + 4*tx + 64*p + j  (p=0..1, j=0..3)
// s pairs come straight from natural ssm (LDS.128); w is staged duplicated
// (w,w) once per tile, so per c: 2 LDS.128 (s) + 2 LDS.128 (wdup) + 32 FFMA2.
// ---------------------------------------------------------------------------
__global__ void __launch_bounds__(256, 2) gemm_kernel(float* __restrict__ out)
{
    __shared__ float  ssm[Cc][128];    // [c][t_local] natural, 16 KB
    __shared__ float2 wdup[Cc][128];   // [c][e_local] duplicated (w,w), 32 KB

    int tid = threadIdx.x;
    int tx = tid & 15;
    int ty = tid >> 4;
    int b = blockIdx.z;
    int eBase = blockIdx.y * 128;
    int tBase = blockIdx.x * 128;

    // Stage s: 32c x 128t, coalesced float4 over t.
    #pragma unroll
    for (int k = 0; k < 4; k++) {
        int idx = tid + k * 256;          // 0..1023
        int c   = idx >> 5;               // 0..31
        int tl  = (idx & 31) * 4;         // 0..124
        size_t off = ((size_t)(b * Cc + c)) * Tt + tBase + tl;
        float4 a  = *(const float4*)(g_sA + off);
        float4 bq = *(const float4*)(g_sB + off);
        *(float4*)&ssm[c][tl] = make_float4(a.x + bq.x, a.y + bq.y,
                                            a.z + bq.z, a.w + bq.w);
    }
    // Stage w duplicated: 32c x 128e -> (w,w) pairs.
    #pragma unroll
    for (int k = 0; k < 4; k++) {
        int idx = tid + k * 256;
        int c   = idx >> 5;
        int e4  = (idx & 31) * 4;
        float4 w = *(const float4*)(g_wc + (size_t)c * Dd + eBase + e4);
        float4* dst = (float4*)&wdup[c][e4];
        dst[0] = make_float4(w.x, w.x, w.y, w.y);
        dst[1] = make_float4(w.z, w.z, w.w, w.w);
    }
    __syncthreads();

    unsigned long long acc[4][8];      // [t-pair i][e index k=p*4+j]
    #pragma unroll
    for (int i = 0; i < 4; i++)
        #pragma unroll
        for (int k = 0; k < 8; k++) acc[i][k] = 0ull;

    #pragma unroll
    for (int c = 0; c < Cc; c++) {
        // s pairs: 8 consecutive t values = 4 f32x2 pairs, natural layout.
        const ulonglong2* sp = (const ulonglong2*)&ssm[c][ty * 8];
        ulonglong2 sa = sp[0];
        ulonglong2 sb = sp[1];
        unsigned long long sv[4] = {sa.x, sa.y, sb.x, sb.y};
        // w dup pairs: e = 4tx..4tx+3 and +64, pre-duplicated.
        const ulonglong2* wq0 = (const ulonglong2*)&wdup[c][4 * tx];
        const ulonglong2* wq1 = (const ulonglong2*)&wdup[c][4 * tx + 64];
        ulonglong2 wa = wq0[0];
        ulonglong2 wb = wq0[1];
        ulonglong2 wc2 = wq1[0];
        ulonglong2 wd = wq1[1];
        unsigned long long wv[8] = {wa.x, wa.y, wb.x, wb.y,
                                    wc2.x, wc2.y, wd.x, wd.y};
        #pragma unroll
        for (int i = 0; i < 4; i++)
            #pragma unroll
            for (int k = 0; k < 8; k++)
                FMA_F32X2(acc[i][k], sv[i], wv[k], acc[i][k]);
    }

    float4 bias0 = *(const float4*)(g_bcomb + eBase + 4 * tx);
    float4 bias1 = *(const float4*)(g_bcomb + eBase + 4 * tx + 64);

    #pragma unroll
    for (int i = 0; i < 4; i++) {
        float2 u[8];
        #pragma unroll
        for (int k = 0; k < 8; k++) u[k] = unpack_f32x2(acc[i][k]);
        int t0 = tBase + ty * 8 + 2 * i;
        float* b0 = out + ((size_t)(b * Tt + t0)) * Dd + eBase;
        float* b1 = b0 + Dd;
        float4 e0 = make_float4(u[0].x + bias0.x, u[1].x + bias0.y,
                                u[2].x + bias0.z, u[3].x + bias0.w);
        float4 e1 = make_float4(u[4].x + bias1.x, u[5].x + bias1.y,
                                u[6].x + bias1.z, u[7].x + bias1.w);
        float4 o0 = make_float4(u[0].y + bias0.x, u[1].y + bias0.y,
                                u[2].y + bias0.z, u[3].y + bias0.w);
        float4 o1 = make_float4(u[4].y + bias1.x, u[5].y + bias1.y,
                                u[6].y + bias1.z, u[7].y + bias1.w);
        *(float4*)(b0 + 4 * tx)      = e0;
        *(float4*)(b0 + 4 * tx + 64) = e1;
        *(float4*)(b1 + 4 * tx)      = o0;
        *(float4*)(b1 + 4 * tx + 64) = o1;
    }
}

// ---------------------------------------------------------------------------
extern "C" void kernel_launch(void* const* d_in, const int* in_sizes, int n_in,
                              void* d_out, int out_size)
{
    const float* x     = (const float*)d_in[0];   // [B, C, T]
    const float* W_ve  = (const float*)d_in[1];   // [D, C]
    const float* b_ve  = (const float*)d_in[2];   // [D]
    const float* W_lin = (const float*)d_in[3];   // [D, D]
    const float* b_lin = (const float*)d_in[4];   // [D]
    float* out = (float*)d_out;                   // [B, T, D]

    scan_kernel<<<(Bb * Cc * NSEG * 2) / 8, 256>>>(x);
    prep_kernel<<<Dd / PE, 256>>>(W_ve, b_ve, W_lin, b_lin);

    dim3 grid(Tt / 128, Dd / 128, Bb);
    gemm_kernel<<<grid, 256>>>(out);
}

// round 14
// speedup vs baseline: 1.5279x; 1.5279x over previous
#include <cuda_runtime.h>
#include <cstdint>

#define Bb 32
#define Cc 32
#define Tt 2048
#define Dd 512
#define ALPHA 0.1f
#define BETA  0.9f

#define SEG   256
#define NSEG  (Tt / SEG)          // 8

// Scratch (no cudaMalloc allowed)
__device__ float g_s[Bb*Cc*Tt];       // 0.5 * (fwd + bwd EWMA of diff)  [b][c][t]
__device__ float g_wc[Cc*Dd];         // Wcomb c-major: g_wc[c*Dd + e]
__device__ float g_bcomb[Dd];         // W_lin @ b_ve + b_lin

#define FMA_F32X2(d, a, b, c) \
    asm("fma.rn.f32x2 %0, %1, %2, %3;" : "=l"(d) : "l"(a), "l"(b), "l"(c))
#define PACK_DUP(d, f) \
    asm("mov.b64 %0, {%1, %1};" : "=l"(d) : "f"(f))

static __device__ __forceinline__ float2 unpack_f32x2(unsigned long long v) {
    float2 r;
    asm("mov.b64 {%0, %1}, %2;" : "=f"(r.x), "=f"(r.y) : "l"(v));
    return r;
}

// ---------------------------------------------------------------------------
// P: smem-tiled mini-GEMM for Wcomb = W_lin @ W_ve (c-major out) + bias.
// (measured ~4us, unchanged)
// ---------------------------------------------------------------------------
#define PE 16
__global__ void __launch_bounds__(256) prep_kernel(
    const float* __restrict__ W_ve, const float* __restrict__ b_ve,
    const float* __restrict__ W_lin, const float* __restrict__ b_lin)
{
    __shared__ float wlin_sm[128 * 17];
    __shared__ float wve_sm[128 * 36];

    int tid = threadIdx.x;
    int e0 = blockIdx.x * PE;
    int tx = tid & 15;
    int ty = tid >> 4;

    float2 acc = make_float2(0.f, 0.f);

    for (int ch = 0; ch < 4; ch++) {
        int dBase = ch * 128;
        __syncthreads();

        #pragma unroll
        for (int k = 0; k < 2; k++) {
            int idx = tid + k * 256;
            int e   = idx >> 5;
            int d4  = (idx & 31) * 4;
            float4 w = *(const float4*)(W_lin + (size_t)(e0 + e) * Dd + dBase + d4);
            wlin_sm[(d4 + 0) * 17 + e] = w.x;
            wlin_sm[(d4 + 1) * 17 + e] = w.y;
            wlin_sm[(d4 + 2) * 17 + e] = w.z;
            wlin_sm[(d4 + 3) * 17 + e] = w.w;
        }
        #pragma unroll
        for (int k = 0; k < 4; k++) {
            int idx = tid + k * 256;
            int d   = idx >> 3;
            int c4  = (idx & 7) * 4;
            float4 v = *(const float4*)(W_ve + (size_t)(dBase + d) * Cc + c4);
            *(float4*)&wve_sm[d * 36 + c4] = v;
        }
        __syncthreads();

        #pragma unroll 8
        for (int dl = 0; dl < 128; dl++) {
            float  wl  = wlin_sm[dl * 17 + ty];
            float2 wv2 = *(const float2*)&wve_sm[dl * 36 + tx * 2];
            acc.x = fmaf(wl, wv2.x, acc.x);
            acc.y = fmaf(wl, wv2.y, acc.y);
        }
    }

    int e = e0 + ty;
    g_wc[(2 * tx)     * Dd + e] = acc.x;
    g_wc[(2 * tx + 1) * Dd + e] = acc.y;

    const unsigned FULL = 0xffffffffu;
    int wid  = tid >> 5;
    int lane = tid & 31;
    #pragma unroll
    for (int r = 0; r < 2; r++) {
        int eb = e0 + 2 * wid + r;
        float a = 0.f;
        #pragma unroll
        for (int i = 0; i < 16; i++) {
            int d = lane + 32 * i;
            a = fmaf(W_lin[(size_t)eb * Dd + d], b_ve[d], a);
        }
        a += __shfl_down_sync(FULL, a, 16);
        a += __shfl_down_sync(FULL, a, 8);
        a += __shfl_down_sync(FULL, a, 4);
        a += __shfl_down_sync(FULL, a, 2);
        a += __shfl_down_sync(FULL, a, 1);
        if (lane == 0) g_bcomb[eb] = a + b_lin[eb];
    }
}

// ---------------------------------------------------------------------------
// S: fused bidirectional EWMA of first-difference. ONE warp per (row,
// segment) computes BOTH directions; results combined in-register via
// shfl_xor(31) (bwd lane l covers fwd lane 31-l's t-range, reversed) and
// written ONCE as 0.5*(f+g) -> halves scratch write + gemm read traffic.
// ---------------------------------------------------------------------------
__global__ void __launch_bounds__(256) scan_kernel(const float* __restrict__ x)
{
    const unsigned FULL = 0xffffffffu;
    int g    = blockIdx.x * 8 + (threadIdx.x >> 5);
    int lane = threadIdx.x & 31;
    int bc   = g >> 3;            // row (b*Cc + c)
    int seg  = g & 7;

    const float* row = x + (size_t)bc * Tt;
    float*      srow = g_s + (size_t)bc * Tt;
    int lo = seg * SEG;
    int hi = lo + SEG;

    const float q   = 0.43046721f;              // 0.9^8
    const float q2  = q * q;
    const float q4  = q2 * q2;
    const float q8  = q4 * q4;
    const float q16 = q8 * q8;
    float blE;
    {
        float p = 1.f, base = q;
        int n = lane;
        while (n) { if (n & 1) p *= base; base *= base; n >>= 1; }
        blE = p;
    }
    const float B256 = 1.9e-12f;

    float Ff[8];                  // forward result, fwd lane layout

    // ---------------- forward pass ----------------
    {
        float warpCarry = 0.f;
        int t0 = (seg == 0) ? lo : (lo - SEG);
        for (; t0 < hi; t0 += SEG) {
            int tb = t0 + lane * 8;
            float4 a  = *(const float4*)(row + tb);
            float4 bq = *(const float4*)(row + tb + 4);
            float e[8] = {a.x, a.y, a.z, a.w, bq.x, bq.y, bq.z, bq.w};
            float prev = __shfl_up_sync(FULL, bq.w, 1);
            if (lane == 0) prev = (tb > 0) ? row[tb - 1] : 0.f;

            float L[8];
            L[0] = (tb == 0) ? 0.f : ALPHA * (e[0] - prev);
            #pragma unroll
            for (int j = 1; j < 8; j++)
                L[j] = fmaf(BETA, L[j - 1], ALPHA * (e[j] - e[j - 1]));

            float v = L[7], vo;
            vo = __shfl_up_sync(FULL, v, 1);  if (lane >= 1)  v = fmaf(q,   vo, v);
            vo = __shfl_up_sync(FULL, v, 2);  if (lane >= 2)  v = fmaf(q2,  vo, v);
            vo = __shfl_up_sync(FULL, v, 4);  if (lane >= 4)  v = fmaf(q4,  vo, v);
            vo = __shfl_up_sync(FULL, v, 8);  if (lane >= 8)  v = fmaf(q8,  vo, v);
            vo = __shfl_up_sync(FULL, v, 16); if (lane >= 16) v = fmaf(q16, vo, v);
            float vprev = __shfl_up_sync(FULL, v, 1);
            if (lane == 0) vprev = 0.f;
            float C = fmaf(blE, warpCarry, vprev);

            float coef = BETA;
            if (t0 >= lo) {
                #pragma unroll
                for (int j = 0; j < 8; j++) { Ff[j] = fmaf(coef, C, L[j]); coef *= BETA; }
            }
            float v31 = __shfl_sync(FULL, v, 31);
            warpCarry = fmaf(B256, warpCarry, v31);
        }
    }

    // ---------------- backward pass + combine ----------------
    {
        bool last = (hi == Tt);
        float warpCarry = last ? (row[Tt - 1] - row[Tt - 2]) : 0.f;
        int tt = last ? (Tt - 1) : (hi + SEG - 1);
        for (; tt >= lo; tt -= SEG) {
            int tb = tt - lane * 8;
            float4 a  = *(const float4*)(row + tb - 7);
            float4 bq = *(const float4*)(row + tb - 3);
            float e[8] = {bq.w, bq.z, bq.y, bq.x, a.w, a.z, a.y, a.x};
            float prev = __shfl_down_sync(FULL, bq.w, 1);
            if (lane == 31) prev = (tb - 8 >= 0) ? row[tb - 8] : 0.f;

            float L[8];
            L[0] = ALPHA * (e[0] - e[1]);
            #pragma unroll
            for (int j = 1; j < 7; j++)
                L[j] = fmaf(BETA, L[j - 1], ALPHA * (e[j] - e[j + 1]));
            {
                float d7 = (tb - 7 == 0) ? 0.f : (e[7] - prev);
                L[7] = fmaf(BETA, L[6], ALPHA * d7);
            }

            float v = L[7], vo;
            vo = __shfl_up_sync(FULL, v, 1);  if (lane >= 1)  v = fmaf(q,   vo, v);
            vo = __shfl_up_sync(FULL, v, 2);  if (lane >= 2)  v = fmaf(q2,  vo, v);
            vo = __shfl_up_sync(FULL, v, 4);  if (lane >= 4)  v = fmaf(q4,  vo, v);
            vo = __shfl_up_sync(FULL, v, 8);  if (lane >= 8)  v = fmaf(q8,  vo, v);
            vo = __shfl_up_sync(FULL, v, 16); if (lane >= 16) v = fmaf(q16, vo, v);
            float vprev = __shfl_up_sync(FULL, v, 1);
            if (lane == 0) vprev = 0.f;
            float C = fmaf(blE, warpCarry, vprev);

            if (tt < hi) {
                // real segment: combine with forward and store once.
                float Fb[8];
                float coef = BETA;
                #pragma unroll
                for (int j = 0; j < 8; j++) { Fb[j] = fmaf(coef, C, L[j]); coef *= BETA; }
                // Exchange: lane l's bwd elements belong to fwd lane 31-l,
                // with element index reversed (j' = 7-j).
                float recv[8];
                #pragma unroll
                for (int j = 0; j < 8; j++)
                    recv[j] = __shfl_xor_sync(FULL, Fb[j], 31);
                int tbf = lo + lane * 8;
                float4 o0 = make_float4(0.5f * (Ff[0] + recv[7]),
                                        0.5f * (Ff[1] + recv[6]),
                                        0.5f * (Ff[2] + recv[5]),
                                        0.5f * (Ff[3] + recv[4]));
                float4 o1 = make_float4(0.5f * (Ff[4] + recv[3]),
                                        0.5f * (Ff[5] + recv[2]),
                                        0.5f * (Ff[6] + recv[1]),
                                        0.5f * (Ff[7] + recv[0]));
                *(float4*)(srow + tbf)     = o0;
                *(float4*)(srow + tbf + 4) = o1;
            }
            float v31 = __shfl_sync(FULL, v, 31);
            warpCarry = fmaf(B256, warpCarry, v31);
        }
    }
}

// ---------------------------------------------------------------------------
// G: register-blocked FFMA2 GEMM (R10 config, measured 45us; s-stage now
// reads the single combined g_s array).
// Block tile 128t x 128e, 256 thr, 2 CTA/SM; thread tile 8t x 8e.
// ---------------------------------------------------------------------------
__global__ void __launch_bounds__(256, 2) gemm_kernel(float* __restrict__ out)
{
    __shared__ float ssm[Cc][128];     // [c][t_local] natural, 16 KB
    __shared__ float wsm[Cc][128];     // [c][e_local] natural, 16 KB

    int tid = threadIdx.x;
    int tx = tid & 15;
    int ty = tid >> 4;
    int b = blockIdx.z;
    int eBase = blockIdx.y * 128;
    int tBase = blockIdx.x * 128;

    // Stage s: 32c x 128t, coalesced float4 over t (single array now).
    #pragma unroll
    for (int k = 0; k < 4; k++) {
        int idx = tid + k * 256;          // 0..1023
        int c   = idx >> 5;               // 0..31
        int tl  = (idx & 31) * 4;         // 0..124
        size_t off = ((size_t)(b * Cc + c)) * Tt + tBase + tl;
        *(float4*)&ssm[c][tl] = *(const float4*)(g_s + off);
    }
    // Stage w: 32c x 128e.
    #pragma unroll
    for (int k = 0; k < 4; k++) {
        int idx = tid + k * 256;
        int c   = idx >> 5;
        int e4  = (idx & 31) * 4;
        *(float4*)&wsm[c][e4] = *(const float4*)(g_wc + (size_t)c * Dd + eBase + e4);
    }
    __syncthreads();

    unsigned long long acc[8][4];
    #pragma unroll
    for (int i = 0; i < 8; i++)
        #pragma unroll
        for (int p = 0; p < 4; p++) acc[i][p] = 0ull;

    #pragma unroll
    for (int c = 0; c < Cc; c++) {
        float4 s0 = *(const float4*)&ssm[c][ty * 8];
        float4 s1 = *(const float4*)&ssm[c][ty * 8 + 4];
        float sf[8] = {s0.x, s0.y, s0.z, s0.w, s1.x, s1.y, s1.z, s1.w};
        unsigned long long sv[8];
        #pragma unroll
        for (int i = 0; i < 8; i++) PACK_DUP(sv[i], sf[i]);

        ulonglong2 w0 = *(const ulonglong2*)&wsm[c][4 * tx];        // e (0,1),(2,3)
        ulonglong2 w1 = *(const ulonglong2*)&wsm[c][4 * tx + 64];
        #pragma unroll
        for (int i = 0; i < 8; i++) {
            FMA_F32X2(acc[i][0], sv[i], w0.x, acc[i][0]);
            FMA_F32X2(acc[i][1], sv[i], w0.y, acc[i][1]);
            FMA_F32X2(acc[i][2], sv[i], w1.x, acc[i][2]);
            FMA_F32X2(acc[i][3], sv[i], w1.y, acc[i][3]);
        }
    }

    float4 bias0 = *(const float4*)(g_bcomb + eBase + 4 * tx);
    float4 bias1 = *(const float4*)(g_bcomb + eBase + 4 * tx + 64);

    #pragma unroll
    for (int i = 0; i < 8; i++) {
        int t = tBase + ty * 8 + i;
        float* base = out + ((size_t)(b * Tt + t)) * Dd + eBase;
        float2 r0 = unpack_f32x2(acc[i][0]);
        float2 r1 = unpack_f32x2(acc[i][1]);
        float2 r2 = unpack_f32x2(acc[i][2]);
        float2 r3 = unpack_f32x2(acc[i][3]);
        float4 o0 = make_float4(r0.x + bias0.x, r0.y + bias0.y,
                                r1.x + bias0.z, r1.y + bias0.w);
        float4 o1 = make_float4(r2.x + bias1.x, r2.y + bias1.y,
                                r3.x + bias1.z, r3.y + bias1.w);
        *(float4*)(base + 4 * tx)      = o0;
        *(float4*)(base + 4 * tx + 64) = o1;
    }
}

// ---------------------------------------------------------------------------
extern "C" void kernel_launch(void* const* d_in, const int* in_sizes, int n_in,
                              void* d_out, int out_size)
{
    const float* x     = (const float*)d_in[0];   // [B, C, T]
    const float* W_ve  = (const float*)d_in[1];   // [D, C]
    const float* b_ve  = (const float*)d_in[2];   // [D]
    const float* W_lin = (const float*)d_in[3];   // [D, D]
    const float* b_lin = (const float*)d_in[4];   // [D]
    float* out = (float*)d_out;                   // [B, T, D]

    // S: 8192 fused-direction warps (rows x 8 segs), 8 warps/block
    scan_kernel<<<(Bb * Cc * NSEG) / 8, 256>>>(x);
    prep_kernel<<<Dd / PE, 256>>>(W_ve, b_ve, W_lin, b_lin);

    dim3 grid(Tt / 128, Dd / 128, Bb);
    gemm_kernel<<<grid, 256>>>(out);
}